// round 2
// baseline (speedup 1.0000x reference)
#include <cuda_runtime.h>
#include <cuda_bf16.h>
#include <cstdint>

// ---------------------------------------------------------------------------
// Problem constants (fixed by the reference)
// ---------------------------------------------------------------------------
#define BATCH   2
#define SEQLEN  1024
#define DMODEL  768
#define DINNER  1536
#define DSTATE  16
#define DTRANK  48
#define XDBL    80          // DTRANK + 2*DSTATE
#define MROWS   (BATCH*SEQLEN)      // 2048

// ---------------------------------------------------------------------------
// Scratch (device globals: no runtime allocation allowed)
// ---------------------------------------------------------------------------
__device__ float g_xz[(size_t)MROWS * 2 * DINNER];        // (2048, 3072)
__device__ float g_xc[2][(size_t)MROWS * DINNER];         // conv+silu out per branch
__device__ float g_xdbl[2][(size_t)MROWS * XDBL];         // dt|B|C per branch
__device__ float g_delta[2][(size_t)MROWS * DINNER];      // softplus(dt_proj)
__device__ float g_y[2][(size_t)MROWS * DINNER];          // scan outputs (branch1 stored un-flipped)

// ---------------------------------------------------------------------------
// K1: 128x128x8 fp32 SGEMM (NT): C[m,n] = sum_k A[m,k]*B[n,k]
//     mode 0: A = hidden (ext), C = g_xz
// ---------------------------------------------------------------------------
__global__ __launch_bounds__(256) void sgemm128_nt(
    const float* __restrict__ Aext, const float* __restrict__ B,
    int M, int N, int K)
{
    const float* A = Aext;
    float* C = g_xz;

    __shared__ float As[8][128];
    __shared__ float Bs[8][128];

    const int tid = threadIdx.x;
    const int m0 = blockIdx.y * 128;
    const int n0 = blockIdx.x * 128;

    const int lr = tid >> 1;          // 0..127
    const int lk = (tid & 1) * 4;     // 0 or 4
    const float* Ap = A + (size_t)(m0 + lr) * K + lk;
    const float* Bp = B + (size_t)(n0 + lr) * K + lk;

    const int ty = tid >> 4;          // 0..15
    const int tx = tid & 15;          // 0..15

    float acc[8][8];
#pragma unroll
    for (int i = 0; i < 8; i++)
#pragma unroll
        for (int j = 0; j < 8; j++) acc[i][j] = 0.f;

    for (int kt = 0; kt < K; kt += 8) {
        float4 av = *(const float4*)(Ap + kt);
        float4 bv = *(const float4*)(Bp + kt);
        __syncthreads();
        As[lk + 0][lr] = av.x; As[lk + 1][lr] = av.y;
        As[lk + 2][lr] = av.z; As[lk + 3][lr] = av.w;
        Bs[lk + 0][lr] = bv.x; Bs[lk + 1][lr] = bv.y;
        Bs[lk + 2][lr] = bv.z; Bs[lk + 3][lr] = bv.w;
        __syncthreads();
#pragma unroll
        for (int k = 0; k < 8; k++) {
            float a[8], b[8];
            *(float4*)(a)     = *(const float4*)&As[k][ty * 8];
            *(float4*)(a + 4) = *(const float4*)&As[k][ty * 8 + 4];
            *(float4*)(b)     = *(const float4*)&Bs[k][tx * 8];
            *(float4*)(b + 4) = *(const float4*)&Bs[k][tx * 8 + 4];
#pragma unroll
            for (int i = 0; i < 8; i++)
#pragma unroll
                for (int j = 0; j < 8; j++)
                    acc[i][j] = fmaf(a[i], b[j], acc[i][j]);
        }
    }

#pragma unroll
    for (int i = 0; i < 8; i++) {
        float* cp = C + (size_t)(m0 + ty * 8 + i) * N + n0 + tx * 8;
        *(float4*)(cp)     = make_float4(acc[i][0], acc[i][1], acc[i][2], acc[i][3]);
        *(float4*)(cp + 4) = make_float4(acc[i][4], acc[i][5], acc[i][6], acc[i][7]);
    }
}

// ---------------------------------------------------------------------------
// K6: 64x64x16 fp32 SGEMM (NT) with fused A = g_y[0] + g_y[1]:
//     out[m,n] = sum_k (y0[m,k]+y1[m,k]) * W[n,k]
// ---------------------------------------------------------------------------
__global__ __launch_bounds__(256) void sgemm64_out(
    const float* __restrict__ B, float* __restrict__ C, int M, int N, int K)
{
    __shared__ float As[16][64];
    __shared__ float Bs[16][64];

    const int tid = threadIdx.x;
    const int m0 = blockIdx.y * 64;
    const int n0 = blockIdx.x * 64;

    const int lr = tid >> 2;          // 0..63
    const int lk = (tid & 3) * 4;     // 0,4,8,12
    const float* A0 = g_y[0] + (size_t)(m0 + lr) * K + lk;
    const float* A1 = g_y[1] + (size_t)(m0 + lr) * K + lk;
    const float* Bp = B + (size_t)(n0 + lr) * K + lk;

    const int ty = tid >> 4;          // 0..15
    const int tx = tid & 15;          // 0..15

    float acc[4][4];
#pragma unroll
    for (int i = 0; i < 4; i++)
#pragma unroll
        for (int j = 0; j < 4; j++) acc[i][j] = 0.f;

    for (int kt = 0; kt < K; kt += 16) {
        float4 av = *(const float4*)(A0 + kt);
        float4 a2 = *(const float4*)(A1 + kt);
        av.x += a2.x; av.y += a2.y; av.z += a2.z; av.w += a2.w;
        float4 bv = *(const float4*)(Bp + kt);
        __syncthreads();
        As[lk + 0][lr] = av.x; As[lk + 1][lr] = av.y;
        As[lk + 2][lr] = av.z; As[lk + 3][lr] = av.w;
        Bs[lk + 0][lr] = bv.x; Bs[lk + 1][lr] = bv.y;
        Bs[lk + 2][lr] = bv.z; Bs[lk + 3][lr] = bv.w;
        __syncthreads();
#pragma unroll
        for (int k = 0; k < 16; k++) {
            float4 a = *(const float4*)&As[k][ty * 4];
            float4 b = *(const float4*)&Bs[k][tx * 4];
            acc[0][0] = fmaf(a.x, b.x, acc[0][0]);
            acc[0][1] = fmaf(a.x, b.y, acc[0][1]);
            acc[0][2] = fmaf(a.x, b.z, acc[0][2]);
            acc[0][3] = fmaf(a.x, b.w, acc[0][3]);
            acc[1][0] = fmaf(a.y, b.x, acc[1][0]);
            acc[1][1] = fmaf(a.y, b.y, acc[1][1]);
            acc[1][2] = fmaf(a.y, b.z, acc[1][2]);
            acc[1][3] = fmaf(a.y, b.w, acc[1][3]);
            acc[2][0] = fmaf(a.z, b.x, acc[2][0]);
            acc[2][1] = fmaf(a.z, b.y, acc[2][1]);
            acc[2][2] = fmaf(a.z, b.z, acc[2][2]);
            acc[2][3] = fmaf(a.z, b.w, acc[2][3]);
            acc[3][0] = fmaf(a.w, b.x, acc[3][0]);
            acc[3][1] = fmaf(a.w, b.y, acc[3][1]);
            acc[3][2] = fmaf(a.w, b.z, acc[3][2]);
            acc[3][3] = fmaf(a.w, b.w, acc[3][3]);
        }
    }

#pragma unroll
    for (int i = 0; i < 4; i++) {
        float* cp = C + (size_t)(m0 + ty * 4 + i) * N + n0 + tx * 4;
        *(float4*)cp = make_float4(acc[i][0], acc[i][1], acc[i][2], acc[i][3]);
    }
}

// ---------------------------------------------------------------------------
// K2: depthwise causal conv (K=4) + SiLU, both branches (branch 1 on reversed L)
// ---------------------------------------------------------------------------
__global__ __launch_bounds__(256) void conv_silu_kernel(
    const float* __restrict__ cw_f, const float* __restrict__ cb_f,
    const float* __restrict__ cw_b, const float* __restrict__ cb_b)
{
    const int m = blockIdx.x;           // 0..2047 (row = b*1024 + t)
    const int br = blockIdx.y;          // 0 fwd, 1 rev
    const int b = m >> 10;
    const int t = m & 1023;
    const float* cw = br ? cw_b : cw_f;
    const float* cb = br ? cb_b : cb_f;

    for (int d = threadIdx.x; d < DINNER; d += 256) {
        float acc = cb[d];
#pragma unroll
        for (int k = 0; k < 4; k++) {
            int tk = t - 3 + k;
            if (tk >= 0) {
                int ls = br ? (SEQLEN - 1 - tk) : tk;
                acc = fmaf(cw[d * 4 + k],
                           g_xz[((size_t)b * SEQLEN + ls) * (2 * DINNER) + d], acc);
            }
        }
        float s = acc / (1.f + __expf(-acc));
        g_xc[br][(size_t)m * DINNER + d] = s;
    }
}

// ---------------------------------------------------------------------------
// K3: x_dbl[m, 0:80] = xc[m,:] @ x_proj_w^T   (x_proj_w: (80,1536))
// ---------------------------------------------------------------------------
__global__ __launch_bounds__(128) void xdbl_kernel(
    const float* __restrict__ xpw_f, const float* __restrict__ xpw_b)
{
    __shared__ float row[DINNER];
    const int m = blockIdx.x;
    const int br = blockIdx.y;
    const float* xc = g_xc[br] + (size_t)m * DINNER;
    for (int i = threadIdx.x; i < DINNER / 4; i += 128)
        *(float4*)&row[i * 4] = *(const float4*)&xc[i * 4];
    __syncthreads();
    if (threadIdx.x < XDBL) {
        const float4* w4 = (const float4*)((br ? xpw_b : xpw_f) + (size_t)threadIdx.x * DINNER);
        float acc = 0.f;
#pragma unroll 4
        for (int k4 = 0; k4 < DINNER / 4; k4++) {
            float4 w = w4[k4];
            const float* r = &row[k4 * 4];
            acc = fmaf(r[0], w.x, acc);
            acc = fmaf(r[1], w.y, acc);
            acc = fmaf(r[2], w.z, acc);
            acc = fmaf(r[3], w.w, acc);
        }
        g_xdbl[br][(size_t)m * XDBL + threadIdx.x] = acc;
    }
}

// ---------------------------------------------------------------------------
// K4: delta[m,d] = softplus(dt[m,:] @ dt_proj_w[d,:]^T + dt_bias[d])
// ---------------------------------------------------------------------------
__global__ __launch_bounds__(256) void delta_kernel(
    const float* __restrict__ dtw_f, const float* __restrict__ dtb_f,
    const float* __restrict__ dtw_b, const float* __restrict__ dtb_b)
{
    __shared__ float sdt[DTRANK];
    const int m = blockIdx.x;
    const int br = blockIdx.y;
    if (threadIdx.x < DTRANK)
        sdt[threadIdx.x] = g_xdbl[br][(size_t)m * XDBL + threadIdx.x];
    __syncthreads();
    const float* dtw = br ? dtw_b : dtw_f;
    const float* dtb = br ? dtb_b : dtb_f;
    for (int d = threadIdx.x; d < DINNER; d += 256) {
        float acc = dtb[d];
        const float4* w4 = (const float4*)(dtw + (size_t)d * DTRANK);
#pragma unroll
        for (int r4 = 0; r4 < DTRANK / 4; r4++) {
            float4 w = w4[r4];
            acc = fmaf(sdt[r4 * 4 + 0], w.x, acc);
            acc = fmaf(sdt[r4 * 4 + 1], w.y, acc);
            acc = fmaf(sdt[r4 * 4 + 2], w.z, acc);
            acc = fmaf(sdt[r4 * 4 + 3], w.w, acc);
        }
        float sp = (acc > 20.f) ? acc : log1pf(__expf(acc));
        g_delta[br][(size_t)m * DINNER + d] = sp;
    }
}

// ---------------------------------------------------------------------------
// K5: selective scan. One 16-lane group per (branch, b, d) channel; lane owns
//     one state n. Per step: h = exp(delta*A_n)*h + delta*x*B_n; y = sum h*C_n.
//     Reverse branch writes un-flipped into g_y[1] (z read un-flipped too).
// ---------------------------------------------------------------------------
__global__ __launch_bounds__(256) void scan_kernel(
    const float* __restrict__ Alog_f, const float* __restrict__ D_f,
    const float* __restrict__ Alog_b, const float* __restrict__ D_b)
{
    const int warp = (blockIdx.x * 256 + threadIdx.x) >> 5;
    const int lane = threadIdx.x & 31;
    const int ch = warp * 2 + (lane >> 4);     // 0..6143
    const int n = lane & 15;
    const int d = ch % DINNER;
    const int bb = ch / DINNER;                // 0..3
    const int b = bb & 1;
    const int br = bb >> 1;

    const float* Alog = br ? Alog_b : Alog_f;
    const float* Dp = br ? D_b : D_f;
    const float Acoef = -__expf(Alog[d * DSTATE + n]);
    const float Dd = Dp[d];

    const size_t base = (size_t)b * SEQLEN;
    const float* dP = g_delta[br] + base * DINNER + d;
    const float* xP = g_xc[br] + base * DINNER + d;
    const float* bP = g_xdbl[br] + base * XDBL + DTRANK + n;
    const float* cP = g_xdbl[br] + base * XDBL + DTRANK + DSTATE + n;

    const float* zP;
    float* yP;
    ptrdiff_t zs, ys;
    if (br == 0) {
        zP = g_xz + base * (2 * DINNER) + DINNER + d;
        zs = 2 * DINNER;
        yP = g_y[0] + base * DINNER + d;
        ys = DINNER;
    } else {
        zP = g_xz + (base + SEQLEN - 1) * (2 * DINNER) + DINNER + d;
        zs = -(ptrdiff_t)(2 * DINNER);
        yP = g_y[1] + (base + SEQLEN - 1) * DINNER + d;
        ys = -(ptrdiff_t)DINNER;
    }

    float h = 0.f;
    for (int t = 0; t < SEQLEN; t++) {
        const float dl = *dP;
        const float xv = *xP;
        const float a = __expf(dl * Acoef);
        const float bv = *bP;
        const float cv = *cP;
        h = fmaf(a, h, dl * xv * bv);
        float yn = h * cv;
        yn += __shfl_xor_sync(0xffffffffu, yn, 1);
        yn += __shfl_xor_sync(0xffffffffu, yn, 2);
        yn += __shfl_xor_sync(0xffffffffu, yn, 4);
        yn += __shfl_xor_sync(0xffffffffu, yn, 8);
        if (n == 0) {
            const float zv = *zP;
            float y = fmaf(xv, Dd, yn);
            y *= zv / (1.f + __expf(-zv));
            *yP = y;
        }
        dP += DINNER; xP += DINNER; bP += XDBL; cP += XDBL;
        zP += zs; yP += ys;
    }
}

// ---------------------------------------------------------------------------
// launch
// ---------------------------------------------------------------------------
extern "C" void kernel_launch(void* const* d_in, const int* in_sizes, int n_in,
                              void* d_out, int out_size)
{
    const float* hidden   = (const float*)d_in[0];
    const float* in_proj  = (const float*)d_in[1];
    const float* conv_w   = (const float*)d_in[2];
    const float* conv_b   = (const float*)d_in[3];
    const float* x_proj_w = (const float*)d_in[4];
    const float* dt_w     = (const float*)d_in[5];
    const float* dt_b     = (const float*)d_in[6];
    const float* A_log    = (const float*)d_in[7];
    const float* Dvec     = (const float*)d_in[8];
    const float* conv_w_b = (const float*)d_in[9];
    const float* conv_b_b = (const float*)d_in[10];
    const float* x_proj_wb= (const float*)d_in[11];
    const float* dt_w_b   = (const float*)d_in[12];
    const float* dt_b_b   = (const float*)d_in[13];
    const float* A_b_log  = (const float*)d_in[14];
    const float* D_b      = (const float*)d_in[15];
    const float* out_w    = (const float*)d_in[16];
    float* out = (float*)d_out;

    // 1) xz = hidden @ in_proj^T     (2048 x 3072, K=768)
    sgemm128_nt<<<dim3((2 * DINNER) / 128, MROWS / 128), 256>>>(
        hidden, in_proj, MROWS, 2 * DINNER, DMODEL);

    // 2) conv + silu (both branches)
    conv_silu_kernel<<<dim3(MROWS, 2), 256>>>(conv_w, conv_b, conv_w_b, conv_b_b);

    // 3) x_dbl = xc @ x_proj^T       (2048 x 80, K=1536)
    xdbl_kernel<<<dim3(MROWS, 2), 128>>>(x_proj_w, x_proj_wb);

    // 4) delta = softplus(dt @ dt_proj^T + bias)   (2048 x 1536, K=48)
    delta_kernel<<<dim3(MROWS, 2), 256>>>(dt_w, dt_b, dt_w_b, dt_b_b);

    // 5) selective scan (both branches), gated output into g_y[0]/g_y[1]
    scan_kernel<<<384, 256>>>(A_log, Dvec, A_b_log, D_b);

    // 6) out = (y_f + y_r) @ out_proj^T   (2048 x 768, K=1536)
    sgemm64_out<<<dim3(DMODEL / 64, MROWS / 64), 256>>>(
        out_w, out, MROWS, DMODEL, DINNER);
}

// round 4
// speedup vs baseline: 3.0627x; 3.0627x over previous
#include <cuda_runtime.h>
#include <cuda_bf16.h>
#include <cstdint>

// ---------------------------------------------------------------------------
// Problem constants
// ---------------------------------------------------------------------------
#define BATCH   2
#define SEQLEN  1024
#define DMODEL  768
#define DINNER  1536
#define DSTATE  16
#define DTRANK  48
#define XDBL    80          // DTRANK + 2*DSTATE
#define MROWS   (BATCH*SEQLEN)      // 2048

// ---------------------------------------------------------------------------
// Scratch (device globals: no runtime allocation allowed)
// ---------------------------------------------------------------------------
__device__ float g_xz[(size_t)MROWS * 2 * DINNER];        // (2048, 3072)
__device__ float g_xc[2][(size_t)MROWS * DINNER];         // conv+silu out per branch
__device__ float g_xdbl[2][(size_t)MROWS * XDBL];         // dt|B|C per branch
__device__ float g_delta[2][(size_t)MROWS * DINNER];      // softplus(dt_proj)
__device__ float g_y[2][(size_t)MROWS * DINNER];          // scan outputs (branch1 un-flipped)

// ---------------------------------------------------------------------------
// K1: 128x128x8 fp32 SGEMM (NT), double-buffered: C = A @ B^T into g_xz
// ---------------------------------------------------------------------------
__global__ __launch_bounds__(256) void sgemm128_nt(
    const float* __restrict__ A, const float* __restrict__ B,
    int M, int N, int K)
{
    float* C = g_xz;
    __shared__ float As[2][8][128];
    __shared__ float Bs[2][8][128];

    const int tid = threadIdx.x;
    const int m0 = blockIdx.y * 128;
    const int n0 = blockIdx.x * 128;

    const int lr = tid >> 1;          // 0..127
    const int lk = (tid & 1) * 4;     // 0 or 4
    const float* Ap = A + (size_t)(m0 + lr) * K + lk;
    const float* Bp = B + (size_t)(n0 + lr) * K + lk;

    const int ty = tid >> 4;          // 0..15
    const int tx = tid & 15;          // 0..15

    float acc[8][8];
#pragma unroll
    for (int i = 0; i < 8; i++)
#pragma unroll
        for (int j = 0; j < 8; j++) acc[i][j] = 0.f;

    const int NT = K / 8;
    {
        float4 av = *(const float4*)(Ap);
        float4 bv = *(const float4*)(Bp);
        As[0][lk + 0][lr] = av.x; As[0][lk + 1][lr] = av.y;
        As[0][lk + 2][lr] = av.z; As[0][lk + 3][lr] = av.w;
        Bs[0][lk + 0][lr] = bv.x; Bs[0][lk + 1][lr] = bv.y;
        Bs[0][lk + 2][lr] = bv.z; Bs[0][lk + 3][lr] = bv.w;
    }
    __syncthreads();

    int buf = 0;
    for (int t = 0; t < NT; t++) {
        float4 av2, bv2;
        const bool more = (t + 1 < NT);
        if (more) {
            av2 = *(const float4*)(Ap + (t + 1) * 8);
            bv2 = *(const float4*)(Bp + (t + 1) * 8);
        }
#pragma unroll
        for (int k = 0; k < 8; k++) {
            float a[8], b[8];
            *(float4*)(a)     = *(const float4*)&As[buf][k][ty * 8];
            *(float4*)(a + 4) = *(const float4*)&As[buf][k][ty * 8 + 4];
            *(float4*)(b)     = *(const float4*)&Bs[buf][k][tx * 8];
            *(float4*)(b + 4) = *(const float4*)&Bs[buf][k][tx * 8 + 4];
#pragma unroll
            for (int i = 0; i < 8; i++)
#pragma unroll
                for (int j = 0; j < 8; j++)
                    acc[i][j] = fmaf(a[i], b[j], acc[i][j]);
        }
        if (more) {
            const int nb = buf ^ 1;
            As[nb][lk + 0][lr] = av2.x; As[nb][lk + 1][lr] = av2.y;
            As[nb][lk + 2][lr] = av2.z; As[nb][lk + 3][lr] = av2.w;
            Bs[nb][lk + 0][lr] = bv2.x; Bs[nb][lk + 1][lr] = bv2.y;
            Bs[nb][lk + 2][lr] = bv2.z; Bs[nb][lk + 3][lr] = bv2.w;
            __syncthreads();
            buf = nb;
        }
    }

#pragma unroll
    for (int i = 0; i < 8; i++) {
        float* cp = C + (size_t)(m0 + ty * 8 + i) * N + n0 + tx * 8;
        *(float4*)(cp)     = make_float4(acc[i][0], acc[i][1], acc[i][2], acc[i][3]);
        *(float4*)(cp + 4) = make_float4(acc[i][4], acc[i][5], acc[i][6], acc[i][7]);
    }
}

// ---------------------------------------------------------------------------
// K6: 64x64x16 fp32 SGEMM (NT), double-buffered, fused A = g_y[0] + g_y[1]
// ---------------------------------------------------------------------------
__global__ __launch_bounds__(256) void sgemm64_out(
    const float* __restrict__ B, float* __restrict__ C, int M, int N, int K)
{
    __shared__ float As[2][16][64];
    __shared__ float Bs[2][16][64];

    const int tid = threadIdx.x;
    const int m0 = blockIdx.y * 64;
    const int n0 = blockIdx.x * 64;

    const int lr = tid >> 2;          // 0..63
    const int lk = (tid & 3) * 4;     // 0,4,8,12
    const float* A0 = g_y[0] + (size_t)(m0 + lr) * K + lk;
    const float* A1 = g_y[1] + (size_t)(m0 + lr) * K + lk;
    const float* Bp = B + (size_t)(n0 + lr) * K + lk;

    const int ty = tid >> 4;          // 0..15
    const int tx = tid & 15;          // 0..15

    float acc[4][4];
#pragma unroll
    for (int i = 0; i < 4; i++)
#pragma unroll
        for (int j = 0; j < 4; j++) acc[i][j] = 0.f;

    const int NT = K / 16;
    {
        float4 av = *(const float4*)(A0);
        float4 a2 = *(const float4*)(A1);
        av.x += a2.x; av.y += a2.y; av.z += a2.z; av.w += a2.w;
        float4 bv = *(const float4*)(Bp);
        As[0][lk + 0][lr] = av.x; As[0][lk + 1][lr] = av.y;
        As[0][lk + 2][lr] = av.z; As[0][lk + 3][lr] = av.w;
        Bs[0][lk + 0][lr] = bv.x; Bs[0][lk + 1][lr] = bv.y;
        Bs[0][lk + 2][lr] = bv.z; Bs[0][lk + 3][lr] = bv.w;
    }
    __syncthreads();

    int buf = 0;
    for (int t = 0; t < NT; t++) {
        float4 av2, bv2;
        const bool more = (t + 1 < NT);
        if (more) {
            const int kt = (t + 1) * 16;
            av2 = *(const float4*)(A0 + kt);
            float4 a2 = *(const float4*)(A1 + kt);
            av2.x += a2.x; av2.y += a2.y; av2.z += a2.z; av2.w += a2.w;
            bv2 = *(const float4*)(Bp + kt);
        }
#pragma unroll
        for (int k = 0; k < 16; k++) {
            float4 a = *(const float4*)&As[buf][k][ty * 4];
            float4 b = *(const float4*)&Bs[buf][k][tx * 4];
            acc[0][0] = fmaf(a.x, b.x, acc[0][0]);
            acc[0][1] = fmaf(a.x, b.y, acc[0][1]);
            acc[0][2] = fmaf(a.x, b.z, acc[0][2]);
            acc[0][3] = fmaf(a.x, b.w, acc[0][3]);
            acc[1][0] = fmaf(a.y, b.x, acc[1][0]);
            acc[1][1] = fmaf(a.y, b.y, acc[1][1]);
            acc[1][2] = fmaf(a.y, b.z, acc[1][2]);
            acc[1][3] = fmaf(a.y, b.w, acc[1][3]);
            acc[2][0] = fmaf(a.z, b.x, acc[2][0]);
            acc[2][1] = fmaf(a.z, b.y, acc[2][1]);
            acc[2][2] = fmaf(a.z, b.z, acc[2][2]);
            acc[2][3] = fmaf(a.z, b.w, acc[2][3]);
            acc[3][0] = fmaf(a.w, b.x, acc[3][0]);
            acc[3][1] = fmaf(a.w, b.y, acc[3][1]);
            acc[3][2] = fmaf(a.w, b.z, acc[3][2]);
            acc[3][3] = fmaf(a.w, b.w, acc[3][3]);
        }
        if (more) {
            const int nb = buf ^ 1;
            As[nb][lk + 0][lr] = av2.x; As[nb][lk + 1][lr] = av2.y;
            As[nb][lk + 2][lr] = av2.z; As[nb][lk + 3][lr] = av2.w;
            Bs[nb][lk + 0][lr] = bv2.x; Bs[nb][lk + 1][lr] = bv2.y;
            Bs[nb][lk + 2][lr] = bv2.z; Bs[nb][lk + 3][lr] = bv2.w;
            __syncthreads();
            buf = nb;
        }
    }

#pragma unroll
    for (int i = 0; i < 4; i++) {
        float* cp = C + (size_t)(m0 + ty * 4 + i) * N + n0 + tx * 4;
        *(float4*)cp = make_float4(acc[i][0], acc[i][1], acc[i][2], acc[i][3]);
    }
}

// ---------------------------------------------------------------------------
// K2: depthwise causal conv (K=4) + SiLU, both branches (branch 1 reversed L)
// ---------------------------------------------------------------------------
__global__ __launch_bounds__(256) void conv_silu_kernel(
    const float* __restrict__ cw_f, const float* __restrict__ cb_f,
    const float* __restrict__ cw_b, const float* __restrict__ cb_b)
{
    const int m = blockIdx.x;
    const int br = blockIdx.y;
    const int b = m >> 10;
    const int t = m & 1023;
    const float* cw = br ? cw_b : cw_f;
    const float* cb = br ? cb_b : cb_f;

    for (int d = threadIdx.x; d < DINNER; d += 256) {
        float acc = cb[d];
        float4 w = *(const float4*)(cw + d * 4);
        float wk[4] = {w.x, w.y, w.z, w.w};
#pragma unroll
        for (int k = 0; k < 4; k++) {
            int tk = t - 3 + k;
            if (tk >= 0) {
                int ls = br ? (SEQLEN - 1 - tk) : tk;
                acc = fmaf(wk[k],
                           g_xz[((size_t)b * SEQLEN + ls) * (2 * DINNER) + d], acc);
            }
        }
        float s = acc / (1.f + __expf(-acc));
        g_xc[br][(size_t)m * DINNER + d] = s;
    }
}

// ---------------------------------------------------------------------------
// K3: x_dbl = xc @ x_proj^T as a tiled GEMM. Block: 32m x 80n, k-tile 16.
//     grid (64, 2). micro = 2m x 5n per thread (256 threads).
// ---------------------------------------------------------------------------
__global__ __launch_bounds__(256) void xdbl_gemm(
    const float* __restrict__ xpw_f, const float* __restrict__ xpw_b)
{
    __shared__ float As[16][32];   // [k][m]
    __shared__ float Bs[16][80];   // [k][n]

    const int br = blockIdx.y;
    const int m0 = blockIdx.x * 32;
    const float* xpw = br ? xpw_b : xpw_f;
    const float* xc = g_xc[br];
    const int tid = threadIdx.x;
    const int ty = tid >> 4;       // 0..15 -> m = ty*2
    const int tx = tid & 15;       // 0..15 -> n = tx*5

    // A-load mapping: 128 float4 (32 rows x 4): threads < 128
    const int arow = tid >> 2;
    const int af = tid & 3;
    // B-load mapping: 320 float4 (80 rows x 4): i0 = tid, i1 = tid+256 (<320 if tid<64)
    const int bn0 = tid >> 2, bf0 = tid & 3;
    const int bn1 = (tid + 256) >> 2, bf1 = (tid + 256) & 3;

    float acc[2][5];
#pragma unroll
    for (int i = 0; i < 2; i++)
#pragma unroll
        for (int j = 0; j < 5; j++) acc[i][j] = 0.f;

    for (int kt = 0; kt < DINNER; kt += 16) {
        float4 va, vb0, vb1;
        if (tid < 128)
            va = *(const float4*)(xc + (size_t)(m0 + arow) * DINNER + kt + af * 4);
        vb0 = *(const float4*)(xpw + (size_t)bn0 * DINNER + kt + bf0 * 4);
        if (tid < 64)
            vb1 = *(const float4*)(xpw + (size_t)bn1 * DINNER + kt + bf1 * 4);
        __syncthreads();
        if (tid < 128) {
            As[af * 4 + 0][arow] = va.x; As[af * 4 + 1][arow] = va.y;
            As[af * 4 + 2][arow] = va.z; As[af * 4 + 3][arow] = va.w;
        }
        Bs[bf0 * 4 + 0][bn0] = vb0.x; Bs[bf0 * 4 + 1][bn0] = vb0.y;
        Bs[bf0 * 4 + 2][bn0] = vb0.z; Bs[bf0 * 4 + 3][bn0] = vb0.w;
        if (tid < 64) {
            Bs[bf1 * 4 + 0][bn1] = vb1.x; Bs[bf1 * 4 + 1][bn1] = vb1.y;
            Bs[bf1 * 4 + 2][bn1] = vb1.z; Bs[bf1 * 4 + 3][bn1] = vb1.w;
        }
        __syncthreads();
#pragma unroll
        for (int k = 0; k < 16; k++) {
            const float a0 = As[k][ty * 2];
            const float a1 = As[k][ty * 2 + 1];
#pragma unroll
            for (int j = 0; j < 5; j++) {
                const float bb = Bs[k][tx * 5 + j];
                acc[0][j] = fmaf(a0, bb, acc[0][j]);
                acc[1][j] = fmaf(a1, bb, acc[1][j]);
            }
        }
    }

#pragma unroll
    for (int i = 0; i < 2; i++)
#pragma unroll
        for (int j = 0; j < 5; j++)
            g_xdbl[br][(size_t)(m0 + ty * 2 + i) * XDBL + tx * 5 + j] = acc[i][j];
}

// ---------------------------------------------------------------------------
// K4: delta = softplus(DT(2048x48) @ dt_proj_w^T(1536x48) + bias).
//     K=48 resident. Block: 64m x 128n, micro 4m x 8n. grid (12, 32, 2).
// ---------------------------------------------------------------------------
__global__ __launch_bounds__(256) void delta_gemm(
    const float* __restrict__ dtw_f, const float* __restrict__ dtb_f,
    const float* __restrict__ dtw_b, const float* __restrict__ dtb_b)
{
    __shared__ float As[48][64];    // [k][m] 12KB
    __shared__ float Bs[48][128];   // [k][n] 24KB

    const int br = blockIdx.z;
    const int m0 = blockIdx.y * 64;
    const int n0 = blockIdx.x * 128;
    const int tid = threadIdx.x;
    const float* dtw = br ? dtw_b : dtw_f;
    const float* dtb = br ? dtb_b : dtb_f;

    // Load A: 64 rows x 48 k (rows of g_xdbl, first 48 cols). 4 thr/row, 3 f4 each.
    {
        const int row = tid >> 2;
        const int f0 = (tid & 3) * 3;
        const float* src = g_xdbl[br] + (size_t)(m0 + row) * XDBL;
#pragma unroll
        for (int f = f0; f < f0 + 3; f++) {
            float4 v = *(const float4*)(src + f * 4);
            As[f * 4 + 0][row] = v.x; As[f * 4 + 1][row] = v.y;
            As[f * 4 + 2][row] = v.z; As[f * 4 + 3][row] = v.w;
        }
    }
    // Load B: 128 rows x 48 k of dtw. 2 thr/row, 6 f4 each.
    {
        const int row = tid >> 1;
        const int f0 = (tid & 1) * 6;
        const float* src = dtw + (size_t)(n0 + row) * DTRANK;
#pragma unroll
        for (int f = f0; f < f0 + 6; f++) {
            float4 v = *(const float4*)(src + f * 4);
            Bs[f * 4 + 0][row] = v.x; Bs[f * 4 + 1][row] = v.y;
            Bs[f * 4 + 2][row] = v.z; Bs[f * 4 + 3][row] = v.w;
        }
    }
    __syncthreads();

    const int ty = tid >> 4;   // 0..15 -> m = ty*4
    const int tx = tid & 15;   // 0..15 -> n = tx*8
    float acc[4][8];
#pragma unroll
    for (int i = 0; i < 4; i++)
#pragma unroll
        for (int j = 0; j < 8; j++) acc[i][j] = 0.f;

#pragma unroll 4
    for (int k = 0; k < 48; k++) {
        float a[4], b[8];
        *(float4*)(a)     = *(const float4*)&As[k][ty * 4];
        *(float4*)(b)     = *(const float4*)&Bs[k][tx * 8];
        *(float4*)(b + 4) = *(const float4*)&Bs[k][tx * 8 + 4];
#pragma unroll
        for (int i = 0; i < 4; i++)
#pragma unroll
            for (int j = 0; j < 8; j++)
                acc[i][j] = fmaf(a[i], b[j], acc[i][j]);
    }

#pragma unroll
    for (int i = 0; i < 4; i++) {
        float* dst = g_delta[br] + (size_t)(m0 + ty * 4 + i) * DINNER + n0 + tx * 8;
#pragma unroll
        for (int j = 0; j < 8; j++) {
            float v = acc[i][j] + dtb[n0 + tx * 8 + j];
            dst[j] = (v > 20.f) ? v : log1pf(__expf(v));
        }
    }
}

// ---------------------------------------------------------------------------
// K5: selective scan, 16-lane group per (branch,b,d), 1-deep load pipeline.
// ---------------------------------------------------------------------------
__global__ __launch_bounds__(256) void scan_kernel(
    const float* __restrict__ Alog_f, const float* __restrict__ D_f,
    const float* __restrict__ Alog_b, const float* __restrict__ D_b)
{
    const int warp = (blockIdx.x * 256 + threadIdx.x) >> 5;
    const int lane = threadIdx.x & 31;
    const int ch = warp * 2 + (lane >> 4);     // 0..6143
    const int n = lane & 15;
    const int d = ch % DINNER;
    const int bb = ch / DINNER;                // 0..3
    const int b = bb & 1;
    const int br = bb >> 1;

    const float* Alog = br ? Alog_b : Alog_f;
    const float* Dp = br ? D_b : D_f;
    const float Acoef = -__expf(Alog[d * DSTATE + n]);
    const float Dd = Dp[d];

    const size_t base = (size_t)b * SEQLEN;
    const float* dP = g_delta[br] + base * DINNER + d;
    const float* xP = g_xc[br] + base * DINNER + d;
    const float* bP = g_xdbl[br] + base * XDBL + DTRANK + n;
    const float* cP = g_xdbl[br] + base * XDBL + DTRANK + DSTATE + n;

    const float* zP;
    float* yP;
    ptrdiff_t zs, ys;
    if (br == 0) {
        zP = g_xz + base * (2 * DINNER) + DINNER + d;
        zs = 2 * DINNER;
        yP = g_y[0] + base * DINNER + d;
        ys = DINNER;
    } else {
        zP = g_xz + (base + SEQLEN - 1) * (2 * DINNER) + DINNER + d;
        zs = -(ptrdiff_t)(2 * DINNER);
        yP = g_y[1] + (base + SEQLEN - 1) * DINNER + d;
        ys = -(ptrdiff_t)DINNER;
    }

    // software pipeline: prefetch next step's operands before computing current
    float dl = *dP, xv = *xP, bv = *bP, cv = *cP, zv = *zP;
    float h = 0.f;
    for (int t = 0; t < SEQLEN; t++) {
        float dl_n, xv_n, bv_n, cv_n, zv_n;
        if (t + 1 < SEQLEN) {
            dl_n = dP[DINNER];
            xv_n = xP[DINNER];
            bv_n = bP[XDBL];
            cv_n = cP[XDBL];
            zv_n = zP[zs];
        } else {
            dl_n = dl; xv_n = xv; bv_n = bv; cv_n = cv; zv_n = zv;
        }
        const float a = __expf(dl * Acoef);
        h = fmaf(a, h, dl * xv * bv);
        float yn = h * cv;
        yn += __shfl_xor_sync(0xffffffffu, yn, 1);
        yn += __shfl_xor_sync(0xffffffffu, yn, 2);
        yn += __shfl_xor_sync(0xffffffffu, yn, 4);
        yn += __shfl_xor_sync(0xffffffffu, yn, 8);
        if (n == 0) {
            float y = fmaf(xv, Dd, yn);
            y *= zv / (1.f + __expf(-zv));
            *yP = y;
        }
        dP += DINNER; xP += DINNER; bP += XDBL; cP += XDBL;
        zP += zs; yP += ys;
        dl = dl_n; xv = xv_n; bv = bv_n; cv = cv_n; zv = zv_n;
    }
}

// ---------------------------------------------------------------------------
// launch
// ---------------------------------------------------------------------------
extern "C" void kernel_launch(void* const* d_in, const int* in_sizes, int n_in,
                              void* d_out, int out_size)
{
    const float* hidden   = (const float*)d_in[0];
    const float* in_proj  = (const float*)d_in[1];
    const float* conv_w   = (const float*)d_in[2];
    const float* conv_b   = (const float*)d_in[3];
    const float* x_proj_w = (const float*)d_in[4];
    const float* dt_w     = (const float*)d_in[5];
    const float* dt_b     = (const float*)d_in[6];
    const float* A_log    = (const float*)d_in[7];
    const float* Dvec     = (const float*)d_in[8];
    const float* conv_w_b = (const float*)d_in[9];
    const float* conv_b_b = (const float*)d_in[10];
    const float* x_proj_wb= (const float*)d_in[11];
    const float* dt_w_b   = (const float*)d_in[12];
    const float* dt_b_b   = (const float*)d_in[13];
    const float* A_b_log  = (const float*)d_in[14];
    const float* D_b      = (const float*)d_in[15];
    const float* out_w    = (const float*)d_in[16];
    float* out = (float*)d_out;

    // 1) xz = hidden @ in_proj^T     (2048 x 3072, K=768)
    sgemm128_nt<<<dim3((2 * DINNER) / 128, MROWS / 128), 256>>>(
        hidden, in_proj, MROWS, 2 * DINNER, DMODEL);

    // 2) conv + silu (both branches)
    conv_silu_kernel<<<dim3(MROWS, 2), 256>>>(conv_w, conv_b, conv_w_b, conv_b_b);

    // 3) x_dbl = xc @ x_proj^T       (2048 x 80, K=1536)
    xdbl_gemm<<<dim3(MROWS / 32, 2), 256>>>(x_proj_w, x_proj_wb);

    // 4) delta = softplus(dt @ dt_proj^T + bias)   (2048 x 1536, K=48)
    delta_gemm<<<dim3(DINNER / 128, MROWS / 64, 2), 256>>>(dt_w, dt_b, dt_w_b, dt_b_b);

    // 5) selective scan (both branches), gated output into g_y[0]/g_y[1]
    scan_kernel<<<384, 256>>>(A_log, Dvec, A_b_log, D_b);

    // 6) out = (y_f + y_r) @ out_proj^T   (2048 x 768, K=1536)
    sgemm64_out<<<dim3(DMODEL / 64, MROWS / 64), 256>>>(
        out_w, out, MROWS, DMODEL, DINNER);
}